// round 1
// baseline (speedup 1.0000x reference)
#include <cuda_runtime.h>
#include <math.h>

#define T_STEPS 512
#define BATCH   64
#define IN_DIM  256
#define HID     512
#define OUT_DIM 256
#define BH      (BATCH * HID)        // 32768
#define M_ROWS  (T_STEPS * BATCH)    // 32768

// Scratch (allocation-free rule: __device__ globals)
__device__ float g_xp[(size_t)M_ROWS * HID];   // 64 MB: xp = x@W_ih^T + b_ih + b_hh
__device__ float g_rnn[(size_t)M_ROWS * HID];  // 64 MB: rnn_out (also serves as h ring)
__device__ unsigned g_bar_cnt = 0;
__device__ unsigned g_bar_gen = 0;

// -------------------- software grid barrier --------------------
__device__ __forceinline__ void grid_sync(unsigned nblocks) {
    __syncthreads();
    if (threadIdx.x == 0) {
        unsigned gen = *(volatile unsigned*)&g_bar_gen;
        __threadfence();                       // make my writes visible before arrival
        unsigned ticket = atomicAdd(&g_bar_cnt, 1);
        if (ticket == nblocks - 1) {
            g_bar_cnt = 0;
            __threadfence();                   // reset visible before release
            atomicExch(&g_bar_gen, gen + 1);   // release
        } else {
            while (*(volatile unsigned*)&g_bar_gen == gen) { }
        }
        __threadfence();                       // acquire
    }
    __syncthreads();
}

// -------------------- SGEMM: C[M,N] = A[M,K] @ Bw[N,K]^T + bias --------------------
template<int BM, int BN, int BK, int TM, int TN, int THREADS>
__global__ __launch_bounds__(THREADS)
void sgemm_bt_bias(const float* __restrict__ A,
                   const float* __restrict__ Bw,
                   const float* __restrict__ bias0,
                   const float* __restrict__ bias1,   // may be nullptr
                   float* __restrict__ C,
                   int M, int N, int K)
{
    __shared__ float As[BK][BM];
    __shared__ float Bs[BK][BN];

    const int tid = threadIdx.x;
    const int tx  = tid % (BN / TN);   // 16
    const int ty  = tid / (BN / TN);   // 16
    const int m0  = blockIdx.y * BM;
    const int n0  = blockIdx.x * BN;

    float acc[TM][TN];
    #pragma unroll
    for (int i = 0; i < TM; ++i)
        #pragma unroll
        for (int j = 0; j < TN; ++j) acc[i][j] = 0.f;

    for (int k0 = 0; k0 < K; k0 += BK) {
        // load A tile: BM x BK as float4 (transposed store)
        #pragma unroll
        for (int i = tid; i < (BM * BK) / 4; i += THREADS) {
            int r  = i / (BK / 4);
            int c4 = i % (BK / 4);
            float4 v = *(const float4*)&A[(size_t)(m0 + r) * K + k0 + c4 * 4];
            As[c4 * 4 + 0][r] = v.x;
            As[c4 * 4 + 1][r] = v.y;
            As[c4 * 4 + 2][r] = v.z;
            As[c4 * 4 + 3][r] = v.w;
        }
        // load B tile: BN x BK as float4 (transposed store)
        #pragma unroll
        for (int i = tid; i < (BN * BK) / 4; i += THREADS) {
            int r  = i / (BK / 4);
            int c4 = i % (BK / 4);
            float4 v = *(const float4*)&Bw[(size_t)(n0 + r) * K + k0 + c4 * 4];
            Bs[c4 * 4 + 0][r] = v.x;
            Bs[c4 * 4 + 1][r] = v.y;
            Bs[c4 * 4 + 2][r] = v.z;
            Bs[c4 * 4 + 3][r] = v.w;
        }
        __syncthreads();

        #pragma unroll
        for (int kk = 0; kk < BK; ++kk) {
            float aR[TM], bR[TN];
            #pragma unroll
            for (int i = 0; i < TM; ++i) aR[i] = As[kk][ty * TM + i];
            #pragma unroll
            for (int j = 0; j < TN; ++j) bR[j] = Bs[kk][tx * TN + j];
            #pragma unroll
            for (int i = 0; i < TM; ++i)
                #pragma unroll
                for (int j = 0; j < TN; ++j)
                    acc[i][j] += aR[i] * bR[j];
        }
        __syncthreads();
    }

    float bj[TN];
    #pragma unroll
    for (int j = 0; j < TN; ++j) {
        int n = n0 + tx * TN + j;
        bj[j] = bias0[n] + (bias1 ? bias1[n] : 0.f);
    }
    #pragma unroll
    for (int i = 0; i < TM; ++i) {
        int m = m0 + ty * TM + i;
        #pragma unroll
        for (int j = 0; j < TN; ++j) {
            int n = n0 + tx * TN + j;
            C[(size_t)m * N + n] = acc[i][j] + bj[j];
        }
    }
}

// -------------------- recurrent scan (persistent, grid-synced) --------------------
#define SCAN_CTAS   128
#define COLS_PER_CTA (HID / SCAN_CTAS)   // 4
#define W_STRIDE    520                  // pad to kill bank conflicts (520 % 32 = 8, rows offset)

__global__ __launch_bounds__(256)
void rnn_scan(const float* __restrict__ Whh,   // [HID, HID]
              float* __restrict__ h_out)       // [BATCH, HID] (d_out tail)
{
    __shared__ float sW[COLS_PER_CTA][W_STRIDE];

    const int tid = threadIdx.x;
    const int c   = tid & 3;          // 0..3 (column within CTA)
    const int b   = tid >> 2;         // 0..63 (batch row)
    const int c0  = blockIdx.x * COLS_PER_CTA;
    const int colg = c0 + c;

    // cache this CTA's W_hh column slice in shared memory (rows = output cols)
    for (int i = tid; i < COLS_PER_CTA * HID; i += 256) {
        int j = i >> 9;          // / 512
        int k = i & (HID - 1);   // % 512
        sW[j][k] = Whh[(size_t)(c0 + j) * HID + k];
    }
    __syncthreads();

    const float4* w4 = (const float4*)sW[c];   // row stride 2080B, 16B aligned

    for (int t = 0; t < T_STEPS; ++t) {
        float acc = g_xp[(size_t)t * BH + (size_t)b * HID + colg];
        if (t > 0) {
            const float4* h4 = (const float4*)&g_rnn[(size_t)(t - 1) * BH + (size_t)b * HID];
            float a0 = 0.f, a1 = 0.f, a2 = 0.f, a3 = 0.f;
            #pragma unroll 4
            for (int k4 = 0; k4 < HID / 4; ++k4) {
                float4 hv = h4[k4];
                float4 wv = w4[k4];
                a0 += hv.x * wv.x;
                a1 += hv.y * wv.y;
                a2 += hv.z * wv.z;
                a3 += hv.w * wv.w;
            }
            acc += (a0 + a1) + (a2 + a3);
        }
        float hn = tanhf(acc);
        g_rnn[(size_t)t * BH + (size_t)b * HID + colg] = hn;
        if (t == T_STEPS - 1)
            h_out[(size_t)b * HID + colg] = hn;
        grid_sync(SCAN_CTAS);
    }
}

// -------------------- launch --------------------
extern "C" void kernel_launch(void* const* d_in, const int* in_sizes, int n_in,
                              void* d_out, int out_size)
{
    const float* x     = (const float*)d_in[0];  // [T,B,I]
    const float* W_ih  = (const float*)d_in[1];  // [H,I]
    const float* W_hh  = (const float*)d_in[2];  // [H,H]
    const float* b_ih  = (const float*)d_in[3];  // [H]
    const float* b_hh  = (const float*)d_in[4];  // [H]
    const float* W_out = (const float*)d_in[5];  // [O,H]
    const float* b_out = (const float*)d_in[6];  // [O]

    float* y = (float*)d_out;                             // [T,B,O]
    float* h = y + (size_t)T_STEPS * BATCH * OUT_DIM;     // [1,B,H]

    float* xp  = nullptr;
    float* rnn = nullptr;
    cudaGetSymbolAddress((void**)&xp,  g_xp);
    cudaGetSymbolAddress((void**)&rnn, g_rnn);

    // K1: xp = x @ W_ih^T + b_ih + b_hh    (M=32768, N=512, K=256)
    {
        dim3 grid(HID / 64, M_ROWS / 128);
        sgemm_bt_bias<128, 64, 16, 8, 4, 256><<<grid, 256>>>(
            x, W_ih, b_ih, b_hh, xp, M_ROWS, HID, IN_DIM);
    }

    // K2: recurrence over T (persistent, grid-synced); writes g_rnn + h_last
    rnn_scan<<<SCAN_CTAS, 256>>>(W_hh, h);

    // K3: y = rnn_out @ W_out^T + b_out    (M=32768, N=256, K=512)
    {
        dim3 grid(OUT_DIM / 64, M_ROWS / 128);
        sgemm_bt_bias<128, 64, 16, 8, 4, 256><<<grid, 256>>>(
            rnn, W_out, b_out, nullptr, y, M_ROWS, OUT_DIM, HID);
    }
}

// round 2
// speedup vs baseline: 1.1248x; 1.1248x over previous
#include <cuda_runtime.h>
#include <math.h>

#define T_STEPS 512
#define BATCH   64
#define IN_DIM  256
#define HID     512
#define OUT_DIM 256
#define BH      (BATCH * HID)        // 32768
#define M_ROWS  (T_STEPS * BATCH)    // 32768

// Scratch (allocation-free rule: __device__ globals)
__device__ float g_xp[(size_t)M_ROWS * HID];   // xp = x@W_ih^T + b_ih + b_hh
__device__ float g_rnn[(size_t)M_ROWS * HID];  // rnn_out (h history)

// ---- atomic-free grid barrier state ----
#define SCAN_CTAS 128
__device__ unsigned g_flags[SCAN_CTAS];  // zero-init; reset at scan end
__device__ unsigned g_gen;               // zero-init; reset at scan end

__device__ __forceinline__ unsigned ld_acq(const unsigned* p) {
    unsigned v;
    asm volatile("ld.acquire.gpu.u32 %0, [%1];" : "=r"(v) : "l"(p));
    return v;
}
__device__ __forceinline__ void st_rel(unsigned* p, unsigned v) {
    asm volatile("st.release.gpu.u32 [%0], %1;" :: "l"(p), "r"(v));
}

// -------------------- SGEMM: C[M,N] = A[M,K] @ Bw[N,K]^T + bias --------------------
template<int BM, int BN, int BK, int TM, int TN, int THREADS>
__global__ __launch_bounds__(THREADS)
void sgemm_bt_bias(const float* __restrict__ A,
                   const float* __restrict__ Bw,
                   const float* __restrict__ bias0,
                   const float* __restrict__ bias1,   // may be nullptr
                   float* __restrict__ C,
                   int M, int N, int K)
{
    __shared__ float As[BK][BM];
    __shared__ float Bs[BK][BN];

    const int tid = threadIdx.x;
    const int tx  = tid % (BN / TN);
    const int ty  = tid / (BN / TN);
    const int m0  = blockIdx.y * BM;
    const int n0  = blockIdx.x * BN;

    float acc[TM][TN];
    #pragma unroll
    for (int i = 0; i < TM; ++i)
        #pragma unroll
        for (int j = 0; j < TN; ++j) acc[i][j] = 0.f;

    for (int k0 = 0; k0 < K; k0 += BK) {
        #pragma unroll
        for (int i = tid; i < (BM * BK) / 4; i += THREADS) {
            int r  = i / (BK / 4);
            int c4 = i % (BK / 4);
            float4 v = *(const float4*)&A[(size_t)(m0 + r) * K + k0 + c4 * 4];
            As[c4 * 4 + 0][r] = v.x;
            As[c4 * 4 + 1][r] = v.y;
            As[c4 * 4 + 2][r] = v.z;
            As[c4 * 4 + 3][r] = v.w;
        }
        #pragma unroll
        for (int i = tid; i < (BN * BK) / 4; i += THREADS) {
            int r  = i / (BK / 4);
            int c4 = i % (BK / 4);
            float4 v = *(const float4*)&Bw[(size_t)(n0 + r) * K + k0 + c4 * 4];
            Bs[c4 * 4 + 0][r] = v.x;
            Bs[c4 * 4 + 1][r] = v.y;
            Bs[c4 * 4 + 2][r] = v.z;
            Bs[c4 * 4 + 3][r] = v.w;
        }
        __syncthreads();

        #pragma unroll
        for (int kk = 0; kk < BK; ++kk) {
            float aR[TM], bR[TN];
            #pragma unroll
            for (int i = 0; i < TM; ++i) aR[i] = As[kk][ty * TM + i];
            #pragma unroll
            for (int j = 0; j < TN; ++j) bR[j] = Bs[kk][tx * TN + j];
            #pragma unroll
            for (int i = 0; i < TM; ++i)
                #pragma unroll
                for (int j = 0; j < TN; ++j)
                    acc[i][j] += aR[i] * bR[j];
        }
        __syncthreads();
    }

    float bj[TN];
    #pragma unroll
    for (int j = 0; j < TN; ++j) {
        int n = n0 + tx * TN + j;
        bj[j] = bias0[n] + (bias1 ? bias1[n] : 0.f);
    }
    #pragma unroll
    for (int i = 0; i < TM; ++i) {
        int m = m0 + ty * TM + i;
        #pragma unroll
        for (int j = 0; j < TN; ++j) {
            int n = n0 + tx * TN + j;
            C[(size_t)m * N + n] = acc[i][j] + bj[j];
        }
    }
}

// -------------------- recurrent scan (persistent, flag-barrier) --------------------
// Grid: 128 CTAs = 64 col-groups x 2 batch-halves.
// CTA (cg, bh): cols [cg*8, cg*8+8), batches [bh*32, bh*32+32).
// 256 threads: c = tid&7, b_local = tid>>3.
#define COLS_PER_CTA 8
#define BATCH_HALF   32
#define W_STRIDE     516   // 516%32=4 -> rows land on distinct banks for float4 reads

__global__ __launch_bounds__(256)
void rnn_scan(const float* __restrict__ Whh,   // [HID, HID]
              float* __restrict__ h_out)       // [BATCH, HID]
{
    __shared__ float sW[COLS_PER_CTA][W_STRIDE];

    const int tid = threadIdx.x;
    const int bid = blockIdx.x;
    const int cg  = bid >> 1;
    const int bh  = bid & 1;
    const int c0  = cg * COLS_PER_CTA;
    const int b0  = bh * BATCH_HALF;

    const int c    = tid & 7;
    const int bl   = tid >> 3;
    const int b    = b0 + bl;
    const int colg = c0 + c;

    // cache W_hh rows c0..c0+7 in SMEM
    for (int i = tid; i < COLS_PER_CTA * HID; i += 256) {
        int r = i >> 9;
        int k = i & (HID - 1);
        sW[r][k] = Whh[(size_t)(c0 + r) * HID + k];
    }
    __syncthreads();

    const float4* w4 = (const float4*)sW[c];

    for (int t = 0; t < T_STEPS; ++t) {
        float acc = g_xp[(size_t)t * BH + (size_t)b * HID + colg];
        if (t > 0) {
            const float4* h4 = (const float4*)&g_rnn[(size_t)(t - 1) * BH + (size_t)b * HID];
            unsigned long long acc01 = 0ull, acc23 = 0ull;  // f32x2 accumulators {0,0}
            #pragma unroll 4
            for (int k4 = 0; k4 < HID / 4; ++k4) {
                float4 hv = h4[k4];
                float4 wv = w4[k4];
                unsigned long long h01, h23, w01, w23;
                asm("mov.b64 %0, {%1, %2};" : "=l"(h01) : "f"(hv.x), "f"(hv.y));
                asm("mov.b64 %0, {%1, %2};" : "=l"(h23) : "f"(hv.z), "f"(hv.w));
                asm("mov.b64 %0, {%1, %2};" : "=l"(w01) : "f"(wv.x), "f"(wv.y));
                asm("mov.b64 %0, {%1, %2};" : "=l"(w23) : "f"(wv.z), "f"(wv.w));
                asm("fma.rn.f32x2 %0, %1, %2, %0;" : "+l"(acc01) : "l"(h01), "l"(w01));
                asm("fma.rn.f32x2 %0, %1, %2, %0;" : "+l"(acc23) : "l"(h23), "l"(w23));
            }
            float s0, s1, s2, s3;
            asm("mov.b64 {%0, %1}, %2;" : "=f"(s0), "=f"(s1) : "l"(acc01));
            asm("mov.b64 {%0, %1}, %2;" : "=f"(s2), "=f"(s3) : "l"(acc23));
            acc += (s0 + s1) + (s2 + s3);
        }
        float hn = tanhf(acc);
        g_rnn[(size_t)t * BH + (size_t)b * HID + colg] = hn;
        if (t == T_STEPS - 1)
            h_out[(size_t)b * HID + colg] = hn;

        // ---- grid barrier (atomic-free, sense = step number) ----
        const unsigned target = (unsigned)t + 1u;
        __syncthreads();
        if (tid == 0)
            st_rel(&g_flags[bid], target);            // publish: my h[t] stores are visible
        if (bid == 0 && tid < 32) {
            // master warp: wait for all 128 flags to reach target
            bool all_ok;
            do {
                unsigned ok = 1u;
                #pragma unroll
                for (int j = 0; j < SCAN_CTAS / 32; ++j)
                    ok &= (ld_acq(&g_flags[tid * (SCAN_CTAS / 32) + j]) >= target) ? 1u : 0u;
                all_ok = __all_sync(0xffffffffu, ok);
            } while (!all_ok);
            if (tid == 0)
                st_rel(&g_gen, target);               // release
        }
        if (tid == 0) {
            while (ld_acq(&g_gen) < target) { }       // acquire
        }
        __syncthreads();
    }

    // reset barrier state for the next graph replay (everyone is past the
    // final barrier; no one polls these again this launch)
    if (tid == 0) {
        st_rel(&g_flags[bid], 0u);
        if (bid == 0) st_rel(&g_gen, 0u);
    }
}

// -------------------- launch --------------------
extern "C" void kernel_launch(void* const* d_in, const int* in_sizes, int n_in,
                              void* d_out, int out_size)
{
    const float* x     = (const float*)d_in[0];  // [T,B,I]
    const float* W_ih  = (const float*)d_in[1];  // [H,I]
    const float* W_hh  = (const float*)d_in[2];  // [H,H]
    const float* b_ih  = (const float*)d_in[3];  // [H]
    const float* b_hh  = (const float*)d_in[4];  // [H]
    const float* W_out = (const float*)d_in[5];  // [O,H]
    const float* b_out = (const float*)d_in[6];  // [O]

    float* y = (float*)d_out;                             // [T,B,O]
    float* h = y + (size_t)T_STEPS * BATCH * OUT_DIM;     // [1,B,H]

    float* xp  = nullptr;
    float* rnn = nullptr;
    cudaGetSymbolAddress((void**)&xp,  g_xp);
    cudaGetSymbolAddress((void**)&rnn, g_rnn);

    // K1: xp = x @ W_ih^T + b_ih + b_hh    (M=32768, N=512, K=256)
    {
        dim3 grid(HID / 64, M_ROWS / 128);
        sgemm_bt_bias<128, 64, 16, 8, 4, 256><<<grid, 256>>>(
            x, W_ih, b_ih, b_hh, xp, M_ROWS, HID, IN_DIM);
    }

    // K2: recurrence over T (persistent, flag-synced); writes g_rnn + h_last
    rnn_scan<<<SCAN_CTAS, 256>>>(W_hh, h);

    // K3: y = rnn_out @ W_out^T + b_out    (M=32768, N=256, K=512)
    {
        dim3 grid(OUT_DIM / 64, M_ROWS / 128);
        sgemm_bt_bias<128, 64, 16, 8, 4, 256><<<grid, 256>>>(
            rnn, W_out, b_out, nullptr, y, M_ROWS, OUT_DIM, HID);
    }
}

// round 3
// speedup vs baseline: 2.0542x; 1.8263x over previous
#include <cuda_runtime.h>
#include <math.h>

#define T_STEPS 512
#define BATCH   64
#define IN_DIM  256
#define HID     512
#define OUT_DIM 256
#define BH      (BATCH * HID)        // 32768
#define M_ROWS  (T_STEPS * BATCH)    // 32768

// Scratch (allocation-free rule: __device__ globals)
__device__ float g_xp[(size_t)M_ROWS * HID];   // xp = x@W_ih^T + b_ih + b_hh
__device__ float g_rnn[(size_t)M_ROWS * HID];  // rnn_out (h history)

// ---- barrier state: monotonic flags + persistent epoch (no resets, no races) ----
#define SCAN_CTAS 128
#define NGROUPS   4     // batch groups (bh)
#define CGS       32    // col groups per batch group
__device__ __align__(128) unsigned g_flags2[NGROUPS][32];  // one 128B line per group
__device__ unsigned g_epoch;                               // advances by T_STEPS per launch

__device__ __forceinline__ unsigned ld_acq(const unsigned* p) {
    unsigned v;
    asm volatile("ld.acquire.gpu.u32 %0, [%1];" : "=r"(v) : "l"(p));
    return v;
}
__device__ __forceinline__ void st_rel(unsigned* p, unsigned v) {
    asm volatile("st.release.gpu.u32 [%0], %1;" :: "l"(p), "r"(v));
}

// -------------------- SGEMM: C[M,N] = A[M,K] @ Bw[N,K]^T + bias --------------------
template<int BM, int BN, int BK, int TM, int TN, int THREADS>
__global__ __launch_bounds__(THREADS)
void sgemm_bt_bias(const float* __restrict__ A,
                   const float* __restrict__ Bw,
                   const float* __restrict__ bias0,
                   const float* __restrict__ bias1,   // may be nullptr
                   float* __restrict__ C,
                   int M, int N, int K)
{
    __shared__ float As[BK][BM];
    __shared__ float Bs[BK][BN];

    const int tid = threadIdx.x;
    const int tx  = tid % (BN / TN);
    const int ty  = tid / (BN / TN);
    const int m0  = blockIdx.y * BM;
    const int n0  = blockIdx.x * BN;

    float acc[TM][TN];
    #pragma unroll
    for (int i = 0; i < TM; ++i)
        #pragma unroll
        for (int j = 0; j < TN; ++j) acc[i][j] = 0.f;

    for (int k0 = 0; k0 < K; k0 += BK) {
        #pragma unroll
        for (int i = tid; i < (BM * BK) / 4; i += THREADS) {
            int r  = i / (BK / 4);
            int c4 = i % (BK / 4);
            float4 v = *(const float4*)&A[(size_t)(m0 + r) * K + k0 + c4 * 4];
            As[c4 * 4 + 0][r] = v.x;
            As[c4 * 4 + 1][r] = v.y;
            As[c4 * 4 + 2][r] = v.z;
            As[c4 * 4 + 3][r] = v.w;
        }
        #pragma unroll
        for (int i = tid; i < (BN * BK) / 4; i += THREADS) {
            int r  = i / (BK / 4);
            int c4 = i % (BK / 4);
            float4 v = *(const float4*)&Bw[(size_t)(n0 + r) * K + k0 + c4 * 4];
            Bs[c4 * 4 + 0][r] = v.x;
            Bs[c4 * 4 + 1][r] = v.y;
            Bs[c4 * 4 + 2][r] = v.z;
            Bs[c4 * 4 + 3][r] = v.w;
        }
        __syncthreads();

        #pragma unroll
        for (int kk = 0; kk < BK; ++kk) {
            float aR[TM], bR[TN];
            #pragma unroll
            for (int i = 0; i < TM; ++i) aR[i] = As[kk][ty * TM + i];
            #pragma unroll
            for (int j = 0; j < TN; ++j) bR[j] = Bs[kk][tx * TN + j];
            #pragma unroll
            for (int i = 0; i < TM; ++i)
                #pragma unroll
                for (int j = 0; j < TN; ++j)
                    acc[i][j] += aR[i] * bR[j];
        }
        __syncthreads();
    }

    float bj[TN];
    #pragma unroll
    for (int j = 0; j < TN; ++j) {
        int n = n0 + tx * TN + j;
        bj[j] = bias0[n] + (bias1 ? bias1[n] : 0.f);
    }
    #pragma unroll
    for (int i = 0; i < TM; ++i) {
        int m = m0 + ty * TM + i;
        #pragma unroll
        for (int j = 0; j < TN; ++j) {
            int n = n0 + tx * TN + j;
            C[(size_t)m * N + n] = acc[i][j] + bj[j];
        }
    }
}

// -------------------- recurrent scan v3 --------------------
// 128 CTAs = 32 col-groups x 4 batch-groups. CTA: 16 cols x 16 batches.
// h[t-1] rows staged in SMEM (coalesced); W slice stationary in SMEM.
// Barrier: per-batch-group (32 CTAs), one-hop, monotonic flags + epoch.
#define COLS_PER_CTA 16
#define BPC          16          // batches per CTA
#define WS           516         // W row stride (floats): 2-way LDS phase worst case
#define HS           520         // H row stride (floats)
#define SMEM_SCAN_BYTES ((COLS_PER_CTA * WS + BPC * HS) * 4)   // 66304

__global__ __launch_bounds__(256)
void rnn_scan3(const float* __restrict__ Whh,   // [HID, HID]
               float* __restrict__ h_out)       // [BATCH, HID]
{
    extern __shared__ float sm[];
    float* sW = sm;                        // [16][WS]
    float* sH = sm + COLS_PER_CTA * WS;    // [16][HS]
    __shared__ unsigned s_base;

    const int tid = threadIdx.x;
    const int bid = blockIdx.x;
    const int bh  = bid & 3;         // batch group
    const int cg  = bid >> 2;        // col group
    const int c   = tid & 15;        // col within CTA
    const int bl  = tid >> 4;        // batch within CTA
    const int colg = cg * COLS_PER_CTA + c;
    const int b    = bh * BPC + bl;
    const int b0   = bh * BPC;

    if (tid == 0) s_base = *(volatile unsigned*)&g_epoch;

    // cache W_hh rows [cg*16, cg*16+16) in SMEM (coalesced float4)
    for (int i = tid; i < COLS_PER_CTA * (HID / 4); i += 256) {
        int r  = i >> 7;          // /128
        int k4 = i & 127;
        float4 v = *(const float4*)&Whh[(size_t)(cg * COLS_PER_CTA + r) * HID + k4 * 4];
        *(float4*)&sW[r * WS + k4 * 4] = v;
    }
    __syncthreads();
    const unsigned base = s_base;

    float my_xp = g_xp[(size_t)b * HID + colg];   // t = 0

    const ulonglong2* h2 = (const ulonglong2*)&sH[bl * HS];
    const ulonglong2* w2 = (const ulonglong2*)&sW[c * WS];

    for (int t = 0; t < T_STEPS; ++t) {
        float acc = my_xp;
        if (t > 0) {
            unsigned long long a01 = 0ull, a23 = 0ull;   // packed f32x2 {0,0}
            #pragma unroll 8
            for (int k4 = 0; k4 < HID / 4; ++k4) {
                ulonglong2 hv = h2[k4];   // LDS.128
                ulonglong2 wv = w2[k4];   // LDS.128
                asm("fma.rn.f32x2 %0, %1, %2, %0;" : "+l"(a01) : "l"(hv.x), "l"(wv.x));
                asm("fma.rn.f32x2 %0, %1, %2, %0;" : "+l"(a23) : "l"(hv.y), "l"(wv.y));
            }
            float s0, s1, s2, s3;
            asm("mov.b64 {%0, %1}, %2;" : "=f"(s0), "=f"(s1) : "l"(a01));
            asm("mov.b64 {%0, %1}, %2;" : "=f"(s2), "=f"(s3) : "l"(a23));
            acc += (s0 + s1) + (s2 + s3);
        }
        float hn = tanhf(acc);
        g_rnn[(size_t)t * BH + (size_t)b * HID + colg] = hn;

        if (t == T_STEPS - 1) {
            h_out[(size_t)b * HID + colg] = hn;
            break;   // no barrier/stage needed after last step
        }

        // ---- group barrier (one-hop, monotonic) ----
        const unsigned target = base + (unsigned)t + 1u;
        __syncthreads();                       // all stores of this CTA issued
        if (tid == 0)
            st_rel(&g_flags2[bh][cg], target); // publish (orders prior stores, gpu scope)
        if (tid < 32) {
            bool ok;
            do {
                unsigned v = ld_acq(&g_flags2[bh][tid]);
                ok = __all_sync(0xffffffffu, (int)(v - target) >= 0);
            } while (!ok);
        }
        __syncthreads();                       // everyone sees group's h[t] published

        // ---- stage h[t] rows b0..b0+15 into SMEM; prefetch next xp ----
        const float* src = &g_rnn[(size_t)t * BH + (size_t)b0 * HID];
        #pragma unroll
        for (int i = tid; i < BPC * (HID / 4); i += 256) {
            int r  = i >> 7;
            int k4 = i & 127;
            float4 v = *(const float4*)&src[(size_t)r * HID + k4 * 4];
            *(float4*)&sH[r * HS + k4 * 4] = v;
        }
        my_xp = g_xp[(size_t)(t + 1) * BH + (size_t)b * HID + colg];
        __syncthreads();
    }

    // advance epoch for the next launch (monotonic flags; stale < new targets)
    if (bid == 0 && tid == 0)
        *(volatile unsigned*)&g_epoch = base + (unsigned)T_STEPS;
}

// -------------------- launch --------------------
extern "C" void kernel_launch(void* const* d_in, const int* in_sizes, int n_in,
                              void* d_out, int out_size)
{
    const float* x     = (const float*)d_in[0];  // [T,B,I]
    const float* W_ih  = (const float*)d_in[1];  // [H,I]
    const float* W_hh  = (const float*)d_in[2];  // [H,H]
    const float* b_ih  = (const float*)d_in[3];  // [H]
    const float* b_hh  = (const float*)d_in[4];  // [H]
    const float* W_out = (const float*)d_in[5];  // [O,H]
    const float* b_out = (const float*)d_in[6];  // [O]

    float* y = (float*)d_out;                             // [T,B,O]
    float* h = y + (size_t)T_STEPS * BATCH * OUT_DIM;     // [1,B,H]

    float* xp  = nullptr;
    float* rnn = nullptr;
    cudaGetSymbolAddress((void**)&xp,  g_xp);
    cudaGetSymbolAddress((void**)&rnn, g_rnn);

    // K1: xp = x @ W_ih^T + b_ih + b_hh    (M=32768, N=512, K=256)
    {
        dim3 grid(HID / 64, M_ROWS / 128);
        sgemm_bt_bias<128, 64, 16, 8, 4, 256><<<grid, 256>>>(
            x, W_ih, b_ih, b_hh, xp, M_ROWS, HID, IN_DIM);
    }

    // K2: recurrence (persistent, group-synced); writes g_rnn + h_last
    cudaFuncSetAttribute(rnn_scan3, cudaFuncAttributeMaxDynamicSharedMemorySize,
                         SMEM_SCAN_BYTES);
    rnn_scan3<<<SCAN_CTAS, 256, SMEM_SCAN_BYTES>>>(W_hh, h);

    // K3: y = rnn_out @ W_out^T + b_out    (M=32768, N=256, K=512)
    {
        dim3 grid(OUT_DIM / 64, M_ROWS / 128);
        sgemm_bt_bias<128, 64, 16, 8, 4, 256><<<grid, 256>>>(
            rnn, W_out, b_out, nullptr, y, M_ROWS, OUT_DIM, HID);
    }
}